// round 4
// baseline (speedup 1.0000x reference)
#include <cuda_runtime.h>

#define NB 16
#define NC 128
#define NHEADS 4
#define ND 32
#define NN 1024
#define FULLM 0xFFFFFFFFu

typedef unsigned long long ull;

// Static device scratch (allocation-free): q*scale, k+r, v — 4MB each.
__device__ __align__(16) float g_q[NB * NHEADS * ND * NN];
__device__ __align__(16) float g_k[NB * NHEADS * ND * NN];
__device__ __align__(16) float g_v[NB * NHEADS * ND * NN];

// ---- packed fp32x2 helpers (SASS FFMA2 — PTX-only pattern) -----------------
__device__ __forceinline__ ull fma2(ull a, ull b, ull c) {
    ull d;
    asm("fma.rn.f32x2 %0, %1, %2, %3;" : "=l"(d) : "l"(a), "l"(b), "l"(c));
    return d;
}
__device__ __forceinline__ ull dup2(float x) {
    ull r;
    asm("mov.b64 %0, {%1, %1};" : "=l"(r) : "f"(x));
    return r;
}
__device__ __forceinline__ float2 unpk2(ull v) {
    float2 f;
    asm("mov.b64 {%0, %1}, %2;" : "=f"(f.x), "=f"(f.y) : "l"(v));
    return f;
}

// ---------------------------------------------------------------------------
// Kernel 1: QKV projection + relative-position fold into K (f32x2 mainloop).
// ---------------------------------------------------------------------------
__global__ __launch_bounds__(256) void qkv_kernel(
    const float* __restrict__ x, const float* __restrict__ Wq,
    const float* __restrict__ rw, const float* __restrict__ rh)
{
    __shared__ float Ws[64][33];   // [o][c] chunk, padded
    __shared__ float xs[32][64];   // [c][n] chunk

    int t  = threadIdx.x;
    int n0 = blockIdx.x * 64;
    int o0 = blockIdx.y * 64;
    int b  = blockIdx.z;
    int ti = t >> 4, tj = t & 15;

    ull acc2[4][2];
#pragma unroll
    for (int k = 0; k < 4; k++) { acc2[k][0] = 0ull; acc2[k][1] = 0ull; }

    for (int kc = 0; kc < 128; kc += 32) {
        __syncthreads();
#pragma unroll
        for (int k = 0; k < 2; k++) {
            int f  = t * 2 + k;
            int oo = f >> 3, c4 = (f & 7) * 4;
            float4 w = *(const float4*)&Wq[(o0 + oo) * 128 + kc + c4];
            Ws[oo][c4 + 0] = w.x; Ws[oo][c4 + 1] = w.y;
            Ws[oo][c4 + 2] = w.z; Ws[oo][c4 + 3] = w.w;
            int cc = f >> 4, nb = (f & 15) * 4;
            *(float4*)&xs[cc][nb] =
                *(const float4*)&x[(size_t)b * NC * NN + (size_t)(kc + cc) * NN + n0 + nb];
        }
        __syncthreads();
#pragma unroll
        for (int cc = 0; cc < 32; ++cc) {
            ulonglong2 xp = *(const ulonglong2*)&xs[cc][tj * 4];  // (x0,x1),(x2,x3)
#pragma unroll
            for (int k = 0; k < 4; k++) {
                ull qd = dup2(Ws[ti * 4 + k][cc]);
                acc2[k][0] = fma2(qd, xp.x, acc2[k][0]);
                acc2[k][1] = fma2(qd, xp.y, acc2[k][1]);
            }
        }
    }

    const float scale = 0.17677669529663689f;  // 1/sqrt(32)
    int s  = o0 >> 7;              // 0=q, 1=k, 2=v
    int n  = n0 + tj * 4;
    int hh = n >> 5, w0 = n & 31;
#pragma unroll
    for (int k = 0; k < 4; k++) {
        int o  = o0 + ti * 4 + k;
        int oh = o & 127;
        int h  = oh >> 5, dd = oh & 31;
        float2 lo = unpk2(acc2[k][0]), hi = unpk2(acc2[k][1]);
        float4 v = make_float4(lo.x, lo.y, hi.x, hi.y);
        if (s == 1) {  // fold relative position into K
            int rbase = (h * ND + dd) * 32;
            float rhv = rh[rbase + hh];
            v.x += rw[rbase + w0 + 0] + rhv;
            v.y += rw[rbase + w0 + 1] + rhv;
            v.z += rw[rbase + w0 + 2] + rhv;
            v.w += rw[rbase + w0 + 3] + rhv;
        } else if (s == 0) {  // pre-scale q
            v.x *= scale; v.y *= scale; v.z *= scale; v.w *= scale;
        }
        float* dst = (s == 0) ? g_q : (s == 1) ? g_k : g_v;
        *(float4*)&dst[((size_t)(b * NHEADS + h) * ND + dd) * NN + n] = v;
    }
}

// ---------------------------------------------------------------------------
// Kernel 2: flash attention, no-max softmax (logit range << 88), f32x2 math.
// CTA = (b, h, 64-query tile); 16 key tiles of 64; 256 threads (8 warps).
// Pass A: warp owns 8 q-rows, lane owns 2 k-cols (register S, 0.56 B/FLOP).
// Pass C: thread owns (i, 8 d) with transposed V tile for packed loads.
// ---------------------------------------------------------------------------
__global__ __launch_bounds__(256) void attn_kernel(float* __restrict__ out)
{
    __shared__ float qs[32][64];
    __shared__ float ks[32][64];
    __shared__ float vsT[64][36];   // [j][d], pitch 36 (16B-aligned d0 in {0,8,16,24})
    __shared__ float Ssh[64][68];   // P tile, pitch 68 (conflict-free row float4)
    __shared__ float lrow[64];

    int t  = threadIdx.x;
    int w  = t >> 5, l = t & 31;
    int it = blockIdx.x & 15;
    int bh = blockIdx.x >> 4;
    int i0 = it * 64;
    int ib = 8 * w;                       // this warp's first query row
    int iown = t & 63, dd0 = (t >> 6) * 8;

    const float* qb = g_q + (size_t)bh * ND * NN;
    const float* kb = g_k + (size_t)bh * ND * NN;
    const float* vb = g_v + (size_t)bh * ND * NN;

#pragma unroll
    for (int k = 0; k < 2; k++) {
        int f  = t * 2 + k;
        int dd = f >> 4, ic = (f & 15) * 4;
        *(float4*)&qs[dd][ic] = *(const float4*)&qb[dd * NN + i0 + ic];
    }
    if (t < 64) lrow[t] = 0.f;

    ull oacc[4];
#pragma unroll
    for (int k = 0; k < 4; k++) oacc[k] = 0ull;

    for (int jt = 0; jt < 16; ++jt) {
        int j0 = jt * 64;
        __syncthreads();   // prior pass C done with vsT/Ssh
#pragma unroll
        for (int k = 0; k < 2; k++) {
            int f  = t * 2 + k;
            int dd = f >> 4, jc = (f & 15) * 4;
            *(float4*)&ks[dd][jc] = *(const float4*)&kb[dd * NN + j0 + jc];
            float4 vv = *(const float4*)&vb[dd * NN + j0 + jc];
            vsT[jc + 0][dd] = vv.x; vsT[jc + 1][dd] = vv.y;
            vsT[jc + 2][dd] = vv.z; vsT[jc + 3][dd] = vv.w;
        }
        __syncthreads();

        // ---- Pass A: S = q^T k' in registers (8 rows x 2 cols per lane) ----
        ull a00 = 0ull, a01 = 0ull, a10 = 0ull, a11 = 0ull;
        ull a20 = 0ull, a21 = 0ull, a30 = 0ull, a31 = 0ull;
#pragma unroll
        for (int cc = 0; cc < 32; ++cc) {
            ulonglong2 qA = *(const ulonglong2*)&qs[cc][ib];      // rows 0-3 (2 pairs)
            ulonglong2 qB = *(const ulonglong2*)&qs[cc][ib + 4];  // rows 4-7
            float2 kv = *(const float2*)&ks[cc][2 * l];
            ull k0 = dup2(kv.x), k1 = dup2(kv.y);
            a00 = fma2(qA.x, k0, a00); a01 = fma2(qA.x, k1, a01);
            a10 = fma2(qA.y, k0, a10); a11 = fma2(qA.y, k1, a11);
            a20 = fma2(qB.x, k0, a20); a21 = fma2(qB.x, k1, a21);
            a30 = fma2(qB.y, k0, a30); a31 = fma2(qB.y, k1, a31);
        }

        // ---- exp (no max-subtract), store P, row-sum reduce ----
        float rs[8];
        {
            float2 e0, e1;
            e0 = unpk2(a00); e1 = unpk2(a01);
            e0.x = __expf(e0.x); e0.y = __expf(e0.y);
            e1.x = __expf(e1.x); e1.y = __expf(e1.y);
            *(float2*)&Ssh[ib + 0][2 * l] = make_float2(e0.x, e1.x);
            *(float2*)&Ssh[ib + 1][2 * l] = make_float2(e0.y, e1.y);
            rs[0] = e0.x + e1.x; rs[1] = e0.y + e1.y;
            e0 = unpk2(a10); e1 = unpk2(a11);
            e0.x = __expf(e0.x); e0.y = __expf(e0.y);
            e1.x = __expf(e1.x); e1.y = __expf(e1.y);
            *(float2*)&Ssh[ib + 2][2 * l] = make_float2(e0.x, e1.x);
            *(float2*)&Ssh[ib + 3][2 * l] = make_float2(e0.y, e1.y);
            rs[2] = e0.x + e1.x; rs[3] = e0.y + e1.y;
            e0 = unpk2(a20); e1 = unpk2(a21);
            e0.x = __expf(e0.x); e0.y = __expf(e0.y);
            e1.x = __expf(e1.x); e1.y = __expf(e1.y);
            *(float2*)&Ssh[ib + 4][2 * l] = make_float2(e0.x, e1.x);
            *(float2*)&Ssh[ib + 5][2 * l] = make_float2(e0.y, e1.y);
            rs[4] = e0.x + e1.x; rs[5] = e0.y + e1.y;
            e0 = unpk2(a30); e1 = unpk2(a31);
            e0.x = __expf(e0.x); e0.y = __expf(e0.y);
            e1.x = __expf(e1.x); e1.y = __expf(e1.y);
            *(float2*)&Ssh[ib + 6][2 * l] = make_float2(e0.x, e1.x);
            *(float2*)&Ssh[ib + 7][2 * l] = make_float2(e0.y, e1.y);
            rs[6] = e0.x + e1.x; rs[7] = e0.y + e1.y;
        }
#pragma unroll
        for (int r = 0; r < 8; r++) {
#pragma unroll
            for (int off = 16; off >= 1; off >>= 1)
                rs[r] += __shfl_xor_sync(FULLM, rs[r], off);
        }
        if (l == 0) {   // rows ib..ib+7 are warp-exclusive: race-free
#pragma unroll
            for (int r = 0; r < 8; r++) lrow[ib + r] += rs[r];
        }
        __syncthreads();

        // ---- Pass C: O += P V^T (packed over d-pairs) ----
#pragma unroll
        for (int j4 = 0; j4 < 16; j4++) {
            float4 p4 = *(const float4*)&Ssh[iown][j4 * 4];
#pragma unroll
            for (int m = 0; m < 4; m++) {
                float pm = (m == 0) ? p4.x : (m == 1) ? p4.y : (m == 2) ? p4.z : p4.w;
                ull pp = dup2(pm);
                ulonglong2 vA = *(const ulonglong2*)&vsT[j4 * 4 + m][dd0];
                ulonglong2 vB = *(const ulonglong2*)&vsT[j4 * 4 + m][dd0 + 4];
                oacc[0] = fma2(pp, vA.x, oacc[0]);
                oacc[1] = fma2(pp, vA.y, oacc[1]);
                oacc[2] = fma2(pp, vB.x, oacc[2]);
                oacc[3] = fma2(pp, vB.y, oacc[3]);
            }
        }
    }
    __syncthreads();

    float inv = 1.f / lrow[iown];
    int b = bh >> 2, h = bh & 3;
    size_t ob = ((size_t)(b * NC + h * ND + dd0)) * NN + i0 + iown;
#pragma unroll
    for (int k = 0; k < 4; k++) {
        float2 o2 = unpk2(oacc[k]);
        out[ob + (size_t)(2 * k + 0) * NN] = o2.x * inv;
        out[ob + (size_t)(2 * k + 1) * NN] = o2.y * inv;
    }
}

extern "C" void kernel_launch(void* const* d_in, const int* in_sizes, int n_in,
                              void* d_out, int out_size)
{
    const float* x  = (const float*)d_in[0];
    const float* Wq = (const float*)d_in[1];
    const float* rw = (const float*)d_in[2];
    const float* rh = (const float*)d_in[3];
    float* out = (float*)d_out;

    dim3 g1(NN / 64, (3 * NC) / 64, NB);   // (16, 6, 16)
    qkv_kernel<<<g1, 256>>>(x, Wq, rw, rh);

    attn_kernel<<<NB * NHEADS * (NN / 64), 256>>>(out);  // 1024 CTAs
}

// round 7
// speedup vs baseline: 3.5937x; 3.5937x over previous
#include <cuda_runtime.h>
#include <cuda_bf16.h>

#define NB 16
#define NC 128
#define NHEADS 4
#define ND 32
#define NN 1024
#define NBH (NB * NHEADS)
#define FULLM 0xFFFFFFFFu

// Static device scratch (allocation-free).
// q, k': packed (hi,lo) bf16 in one u32, layout [bh][n][d]  (8 MB each)
// v: hi/lo bf16 planes, layout [bh][d][n] stored as u32 j-pairs (4 MB each)
__device__ __align__(16) unsigned g_qpk[NBH * NN * ND];
__device__ __align__(16) unsigned g_kpk[NBH * NN * ND];
__device__ __align__(16) unsigned g_vhi[NBH * ND * (NN / 2)];
__device__ __align__(16) unsigned g_vlo[NBH * ND * (NN / 2)];

// ---------------- bf16 helpers ----------------
__device__ __forceinline__ unsigned pk_split(float x) {
    __nv_bfloat16 h = __float2bfloat16(x);
    float hf = __bfloat162float(h);
    __nv_bfloat16 l = __float2bfloat16(x - hf);
    return (unsigned)__bfloat16_as_ushort(h) | ((unsigned)__bfloat16_as_ushort(l) << 16);
}
__device__ __forceinline__ unsigned pk_hi2(float a, float b) {
    return (unsigned)__bfloat16_as_ushort(__float2bfloat16(a)) |
           ((unsigned)__bfloat16_as_ushort(__float2bfloat16(b)) << 16);
}
// pack2(lo, hi): bf16x2 with lo in bits[0:16)
__device__ __forceinline__ unsigned pack2(float lo, float hi) {
    unsigned r;
    asm("cvt.rn.bf16x2.f32 %0, %1, %2;" : "=r"(r) : "f"(hi), "f"(lo));
    return r;
}

// m16n8k16 bf16 MMA, fp32 accumulate (sm_80+ baseline — legal on compute_103)
__device__ __forceinline__ void mma_bf16(float& c0, float& c1, float& c2, float& c3,
                                         unsigned a0, unsigned a1, unsigned a2, unsigned a3,
                                         unsigned b0, unsigned b1) {
    asm volatile(
        "mma.sync.aligned.m16n8k16.row.col.f32.bf16.bf16.f32 "
        "{%0,%1,%2,%3}, {%4,%5,%6,%7}, {%8,%9}, {%0,%1,%2,%3};"
        : "+f"(c0), "+f"(c1), "+f"(c2), "+f"(c3)
        : "r"(a0), "r"(a1), "r"(a2), "r"(a3), "r"(b0), "r"(b1));
}

// ---------------------------------------------------------------------------
// Kernel 1: QKV projection (fp32) + relative-position fold into K.
// Emits packed/split bf16 operand tensors for the MMA attention kernel.
// ---------------------------------------------------------------------------
__global__ __launch_bounds__(256) void qkv_kernel(
    const float* __restrict__ x, const float* __restrict__ Wq,
    const float* __restrict__ rw, const float* __restrict__ rh)
{
    __shared__ float Ws[64][33];
    __shared__ float xs[32][64];

    int t  = threadIdx.x;
    int n0 = blockIdx.x * 64;
    int o0 = blockIdx.y * 64;
    int b  = blockIdx.z;
    int ti = t >> 4, tj = t & 15;

    float4 acc[4];
#pragma unroll
    for (int k = 0; k < 4; k++) acc[k] = make_float4(0.f, 0.f, 0.f, 0.f);

    for (int kc = 0; kc < 128; kc += 32) {
        __syncthreads();
#pragma unroll
        for (int k = 0; k < 2; k++) {
            int f  = t * 2 + k;
            int oo = f >> 3, c4 = (f & 7) * 4;
            float4 w = *(const float4*)&Wq[(o0 + oo) * 128 + kc + c4];
            Ws[oo][c4 + 0] = w.x; Ws[oo][c4 + 1] = w.y;
            Ws[oo][c4 + 2] = w.z; Ws[oo][c4 + 3] = w.w;
            int cc = f >> 4, nb = (f & 15) * 4;
            *(float4*)&xs[cc][nb] =
                *(const float4*)&x[(size_t)b * NC * NN + (size_t)(kc + cc) * NN + n0 + nb];
        }
        __syncthreads();
#pragma unroll
        for (int cc = 0; cc < 32; ++cc) {
            float4 xv = *(const float4*)&xs[cc][tj * 4];
            float q0 = Ws[ti * 4 + 0][cc];
            float q1 = Ws[ti * 4 + 1][cc];
            float q2 = Ws[ti * 4 + 2][cc];
            float q3 = Ws[ti * 4 + 3][cc];
            acc[0].x = fmaf(q0, xv.x, acc[0].x); acc[0].y = fmaf(q0, xv.y, acc[0].y);
            acc[0].z = fmaf(q0, xv.z, acc[0].z); acc[0].w = fmaf(q0, xv.w, acc[0].w);
            acc[1].x = fmaf(q1, xv.x, acc[1].x); acc[1].y = fmaf(q1, xv.y, acc[1].y);
            acc[1].z = fmaf(q1, xv.z, acc[1].z); acc[1].w = fmaf(q1, xv.w, acc[1].w);
            acc[2].x = fmaf(q2, xv.x, acc[2].x); acc[2].y = fmaf(q2, xv.y, acc[2].y);
            acc[2].z = fmaf(q2, xv.z, acc[2].z); acc[2].w = fmaf(q2, xv.w, acc[2].w);
            acc[3].x = fmaf(q3, xv.x, acc[3].x); acc[3].y = fmaf(q3, xv.y, acc[3].y);
            acc[3].z = fmaf(q3, xv.z, acc[3].z); acc[3].w = fmaf(q3, xv.w, acc[3].w);
        }
    }

    const float scale = 0.17677669529663689f;  // 1/sqrt(32)
    int s  = o0 >> 7;              // 0=q, 1=k, 2=v
    int n  = n0 + tj * 4;
    int hh = n >> 5, w0 = n & 31;
#pragma unroll
    for (int k = 0; k < 4; k++) {
        int o  = o0 + ti * 4 + k;
        int oh = o & 127;
        int h  = oh >> 5, dd = oh & 31;
        int bh = b * NHEADS + h;
        float4 v = acc[k];
        if (s == 1) {          // fold relative position into K
            int rbase = (h * ND + dd) * 32;
            float rhv = rh[rbase + hh];
            v.x += rw[rbase + w0 + 0] + rhv;
            v.y += rw[rbase + w0 + 1] + rhv;
            v.z += rw[rbase + w0 + 2] + rhv;
            v.w += rw[rbase + w0 + 3] + rhv;
            size_t base = ((size_t)bh * NN + n) * ND + dd;
            g_kpk[base + 0 * ND] = pk_split(v.x);
            g_kpk[base + 1 * ND] = pk_split(v.y);
            g_kpk[base + 2 * ND] = pk_split(v.z);
            g_kpk[base + 3 * ND] = pk_split(v.w);
        } else if (s == 0) {   // pre-scale q
            v.x *= scale; v.y *= scale; v.z *= scale; v.w *= scale;
            size_t base = ((size_t)bh * NN + n) * ND + dd;
            g_qpk[base + 0 * ND] = pk_split(v.x);
            g_qpk[base + 1 * ND] = pk_split(v.y);
            g_qpk[base + 2 * ND] = pk_split(v.z);
            g_qpk[base + 3 * ND] = pk_split(v.w);
        } else {               // v: hi/lo planes, [d][n] as u32 j-pairs
            float xh = __bfloat162float(__float2bfloat16(v.x));
            float yh = __bfloat162float(__float2bfloat16(v.y));
            float zh = __bfloat162float(__float2bfloat16(v.z));
            float wh = __bfloat162float(__float2bfloat16(v.w));
            size_t base = ((size_t)bh * ND + dd) * (NN / 2) + (n >> 1);
            g_vhi[base + 0] = pk_hi2(v.x, v.y);
            g_vhi[base + 1] = pk_hi2(v.z, v.w);
            g_vlo[base + 0] = pk_hi2(v.x - xh, v.y - yh);
            g_vlo[base + 1] = pk_hi2(v.z - zh, v.w - wh);
        }
    }
}

// ---------------------------------------------------------------------------
// Kernel 2: flash attention via mma.sync bf16 (fp32-exact split, no-max softmax).
// CTA = 128 threads (4 warps), i-tile 128 (32 rows/warp), 16 j-tiles of 64.
// GEMM1: S = qpk·kpk + swap(qpk)·kpk  (exact (qh+ql)(kh+kl))
// exp + split into Phi/Plo A-fragments IN REGISTERS (FA2 C->A identity)
// GEMM2: O += Phi·Vh + Phi·Vl + Plo·Vh   (register accumulators, all jt)
// ---------------------------------------------------------------------------
__global__ __launch_bounds__(128) void attn_kernel(float* __restrict__ out)
{
    __shared__ unsigned ks[64][33];   // [j][d-pair u32]
    __shared__ unsigned vh[32][33];   // [d][j-pair u32]
    __shared__ unsigned vl[32][33];

    int t    = threadIdx.x;
    int wid  = t >> 5, lane = t & 31;
    int g    = lane >> 2, tq = lane & 3;       // groupID, threadID-in-quad
    int bh   = blockIdx.x >> 3;
    int i0   = (blockIdx.x & 7) * 128;
    int ib   = wid * 32;

    const unsigned* gq  = g_qpk + (size_t)bh * NN * ND;
    const unsigned* gk  = g_kpk + (size_t)bh * NN * ND;
    const unsigned* gvh = g_vhi + (size_t)bh * ND * (NN / 2);
    const unsigned* gvl = g_vlo + (size_t)bh * ND * (NN / 2);

    // --- Q A-fragments (held all kernel): qa[mb][kt][4], plus swapped copy ---
    unsigned qa[32], qsw[32];
#pragma unroll
    for (int mb = 0; mb < 2; mb++) {
        int rg  = i0 + ib + mb * 16 + g;
        int rg8 = rg + 8;
#pragma unroll
        for (int kt = 0; kt < 4; kt++) {
            int c0 = kt * 8 + tq, c4 = c0 + 4;
            unsigned* a = &qa[mb * 16 + kt * 4];
            a[0] = gq[rg  * ND + c0];
            a[1] = gq[rg8 * ND + c0];
            a[2] = gq[rg  * ND + c4];
            a[3] = gq[rg8 * ND + c4];
        }
    }
#pragma unroll
    for (int i = 0; i < 32; i++) qsw[i] = __byte_perm(qa[i], 0, 0x1032);

    float oacc[32];
#pragma unroll
    for (int i = 0; i < 32; i++) oacc[i] = 0.f;
    float lsum[4] = {0.f, 0.f, 0.f, 0.f};   // [mb][row g / g+8]

    for (int jt = 0; jt < 16; ++jt) {
        int j0 = jt * 64;
        __syncthreads();
        // ---- fill K tile (64x32 u32) and V hi/lo tiles (32x32 u32 each) ----
#pragma unroll
        for (int i = 0; i < 16; i++) {
            int idx = t + i * 128;
            ks[idx >> 5][idx & 31] = gk[(j0 + (idx >> 5)) * ND + (idx & 31)];
        }
#pragma unroll
        for (int i = 0; i < 8; i++) {
            int idx = t + i * 128;
            int r = idx >> 5, c = idx & 31;
            vh[r][c] = gvh[(size_t)r * (NN / 2) + (j0 >> 1) + c];
            vl[r][c] = gvl[(size_t)r * (NN / 2) + (j0 >> 1) + c];
        }
        __syncthreads();

        // ---- GEMM1 + exp + P-fragment build ----
        unsigned phi[32], plo[32];
#pragma unroll
        for (int nb = 0; nb < 8; nb++) {
            float c[8];
#pragma unroll
            for (int i = 0; i < 8; i++) c[i] = 0.f;
#pragma unroll
            for (int kt = 0; kt < 4; kt++) {
                unsigned b0 = ks[nb * 8 + g][kt * 8 + tq];
                unsigned b1 = ks[nb * 8 + g][kt * 8 + tq + 4];
#pragma unroll
                for (int mb = 0; mb < 2; mb++) {
                    const unsigned* a = &qa[mb * 16 + kt * 4];
                    const unsigned* s = &qsw[mb * 16 + kt * 4];
                    mma_bf16(c[mb*4], c[mb*4+1], c[mb*4+2], c[mb*4+3],
                             a[0], a[1], a[2], a[3], b0, b1);
                    mma_bf16(c[mb*4], c[mb*4+1], c[mb*4+2], c[mb*4+3],
                             s[0], s[1], s[2], s[3], b0, b1);
                }
            }
            int kt2 = nb >> 1, off = (nb & 1) * 2;
#pragma unroll
            for (int mb = 0; mb < 2; mb++) {
                float p0 = __expf(c[mb*4+0]);
                float p1 = __expf(c[mb*4+1]);
                float p2 = __expf(c[mb*4+2]);
                float p3 = __expf(c[mb*4+3]);
                lsum[mb*2+0] += p0 + p1;
                lsum[mb*2+1] += p2 + p3;
                unsigned hp01 = pack2(p0, p1);
                unsigned hp23 = pack2(p2, p3);
                float h0 = __uint_as_float(hp01 << 16);
                float h1 = __uint_as_float(hp01 & 0xFFFF0000u);
                float h2 = __uint_as_float(hp23 << 16);
                float h3 = __uint_as_float(hp23 & 0xFFFF0000u);
                phi[mb*16 + kt2*4 + off + 0] = hp01;           // rows g   (a0/a2)
                phi[mb*16 + kt2*4 + off + 1] = hp23;           // rows g+8 (a1/a3)
                plo[mb*16 + kt2*4 + off + 0] = pack2(p0 - h0, p1 - h1);
                plo[mb*16 + kt2*4 + off + 1] = pack2(p2 - h2, p3 - h3);
            }
        }

        // ---- GEMM2: O += Phi·Vh + Phi·Vl + Plo·Vh ----
#pragma unroll
        for (int nb2 = 0; nb2 < 4; nb2++) {
#pragma unroll
            for (int kt2 = 0; kt2 < 4; kt2++) {
                unsigned bh0 = vh[nb2 * 8 + g][kt2 * 8 + tq];
                unsigned bh1 = vh[nb2 * 8 + g][kt2 * 8 + tq + 4];
                unsigned bl0 = vl[nb2 * 8 + g][kt2 * 8 + tq];
                unsigned bl1 = vl[nb2 * 8 + g][kt2 * 8 + tq + 4];
#pragma unroll
                for (int mb = 0; mb < 2; mb++) {
                    float* o = &oacc[(mb * 4 + nb2) * 4];
                    const unsigned* ah = &phi[mb * 16 + kt2 * 4];
                    const unsigned* al = &plo[mb * 16 + kt2 * 4];
                    mma_bf16(o[0], o[1], o[2], o[3], ah[0], ah[1], ah[2], ah[3], bh0, bh1);
                    mma_bf16(o[0], o[1], o[2], o[3], ah[0], ah[1], ah[2], ah[3], bl0, bl1);
                    mma_bf16(o[0], o[1], o[2], o[3], al[0], al[1], al[2], al[3], bh0, bh1);
                }
            }
        }
    }

    // ---- finalize: quad-reduce row sums, divide, store ----
#pragma unroll
    for (int i = 0; i < 4; i++) {
        lsum[i] += __shfl_xor_sync(FULLM, lsum[i], 1);
        lsum[i] += __shfl_xor_sync(FULLM, lsum[i], 2);
    }
    int b = bh >> 2, h = bh & 3;
    size_t cbase = (size_t)b * NC + h * ND;
#pragma unroll
    for (int mb = 0; mb < 2; mb++) {
        int rg = i0 + ib + mb * 16 + g;
        float inv0 = 1.f / lsum[mb * 2 + 0];
        float inv1 = 1.f / lsum[mb * 2 + 1];
#pragma unroll
        for (int nb2 = 0; nb2 < 4; nb2++) {
            const float* o = &oacc[(mb * 4 + nb2) * 4];
            int d0 = nb2 * 8 + 2 * tq;
            out[(cbase + d0    ) * NN + rg    ] = o[0] * inv0;
            out[(cbase + d0 + 1) * NN + rg    ] = o[1] * inv0;
            out[(cbase + d0    ) * NN + rg + 8] = o[2] * inv1;
            out[(cbase + d0 + 1) * NN + rg + 8] = o[3] * inv1;
        }
    }
}

extern "C" void kernel_launch(void* const* d_in, const int* in_sizes, int n_in,
                              void* d_out, int out_size)
{
    const float* x  = (const float*)d_in[0];
    const float* Wq = (const float*)d_in[1];
    const float* rw = (const float*)d_in[2];
    const float* rh = (const float*)d_in[3];
    float* out = (float*)d_out;

    dim3 g1(NN / 64, (3 * NC) / 64, NB);
    qkv_kernel<<<g1, 256>>>(x, Wq, rw, rh);

    attn_kernel<<<NBH * 8, 128>>>(out);   // 512 CTAs
}